// round 7
// baseline (speedup 1.0000x reference)
#include <cuda_runtime.h>
#include <cuda_fp16.h>

#define D 64
#define MAXN 100000
#define MAXE 1600000
#define TILE 64          // nodes per combine block
#define RS 66            // padded node stride (floats) in combine smem
#define RS64 33          // same, in u64 units

typedef unsigned long long u64;

// ---------------- static scratch (no allocation allowed) -------------------
__device__ float  g_mean[(size_t)MAXN * D];
__device__ float  g_h[(size_t)MAXN * D];
__device__ __half g_xh[(size_t)MAXN * D];   // fp16 copy of gather operand
__device__ int    g_deg[MAXN];
__device__ int    g_rowptr[MAXN];
__device__ int    g_cursor[MAXN];
__device__ int    g_csrsrc[MAXE];
__device__ int    g_blocksums[128];
__device__ int    g_blockoffs[128];

// ---------------- f32x2 helpers --------------------------------------------
__device__ __forceinline__ u64 fma2(u64 a, u64 b, u64 c) {
    u64 d;
    asm("fma.rn.f32x2 %0, %1, %2, %3;" : "=l"(d) : "l"(a), "l"(b), "l"(c));
    return d;
}
__device__ __forceinline__ u64 pack2(float v) {
    u64 d;
    asm("mov.b64 %0, {%1, %1};" : "=l"(d) : "f"(v));
    return d;
}
__device__ __forceinline__ void unpack2(u64 v, float& lo, float& hi) {
    asm("mov.b64 {%0, %1}, %2;" : "=f"(lo), "=f"(hi) : "l"(v));
}

// ---------------- CSR build ------------------------------------------------
__global__ void count_kernel(const int* __restrict__ dst, int* __restrict__ deg,
                             int n_edges) {
    int e = blockIdx.x * blockDim.x + threadIdx.x;
    if (e < n_edges) atomicAdd(deg + __ldg(dst + e), 1);
}

__global__ void scan_kernel(const int* __restrict__ in, int* __restrict__ out,
                            int* sums, int n) {
    __shared__ int sm[1024];
    int t = threadIdx.x;
    int i = blockIdx.x * 1024 + t;
    int v = (i < n) ? in[i] : 0;
    sm[t] = v;
    __syncthreads();
#pragma unroll
    for (int off = 1; off < 1024; off <<= 1) {
        int add = (t >= off) ? sm[t - off] : 0;
        __syncthreads();
        sm[t] += add;
        __syncthreads();
    }
    if (i < n) out[i] = sm[t] - v;            // exclusive
    if (sums != nullptr && t == 1023) sums[blockIdx.x] = sm[1023];
}

__global__ void add_off_kernel(int* __restrict__ rowptr, int* __restrict__ cursor,
                               const int* __restrict__ boffs, int n) {
    int i = blockIdx.x * blockDim.x + threadIdx.x;
    if (i < n) {
        int v = rowptr[i] + boffs[i >> 10];
        rowptr[i] = v;
        cursor[i] = v;
    }
}

__global__ void fill_kernel(const int* __restrict__ src, const int* __restrict__ dst,
                            int* __restrict__ cursor, int* __restrict__ csr,
                            int n_edges) {
    int e = blockIdx.x * blockDim.x + threadIdx.x;
    if (e < n_edges) {
        int d = __ldg(dst + e);
        int pos = atomicAdd(cursor + d, 1);
        csr[pos] = __ldg(src + e);
    }
}

// ---------------- fp32 -> fp16 conversion (x only) --------------------------
__global__ void convert_kernel(const float4* __restrict__ in,
                               uint2* __restrict__ outh, int n4) {
    int i = blockIdx.x * blockDim.x + threadIdx.x;
    if (i < n4) {
        float4 v = __ldg(in + i);
        __half2 h0 = __floats2half2_rn(v.x, v.y);
        __half2 h1 = __floats2half2_rn(v.z, v.w);
        uint2 o;
        o.x = *(unsigned*)&h0;
        o.y = *(unsigned*)&h1;
        outh[i] = o;
    }
}

// ---------------- aggregate: mean of in-neighbors (fp16 gather) -------------
__global__ void aggregate_kernel(const uint2* __restrict__ xh2,
                                 const int* __restrict__ csr,
                                 const int* __restrict__ rowptr,
                                 const int* __restrict__ deg,
                                 float4* __restrict__ mean4, int n_nodes) {
    int warp = (blockIdx.x * blockDim.x + threadIdx.x) >> 5;
    int n0 = warp * 2;
    if (n0 >= n_nodes) return;
    int lane = threadIdx.x & 31;
    int half = lane >> 4;
    int q = lane & 15;                 // halves 4q..4q+3 of the row
    int node = n0 + half;
    bool valid = node < n_nodes;

    int base = valid ? __ldg(rowptr + node) : 0;
    int dg   = valid ? __ldg(deg + node) : 0;
    int dgA = __shfl_sync(0xffffffffu, dg, 0);
    int dgB = __shfl_sync(0xffffffffu, dg, 16);
    int maxdg = max(dgA, dgB);

    float a0 = 0.f, a1 = 0.f, a2 = 0.f, a3 = 0.f;

    int j = 0;
    for (; j + 8 <= maxdg; j += 8) {
#pragma unroll
        for (int i = 0; i < 8; i++) {
            if (j + i < dg) {
                int s = __ldg(csr + base + j + i);
                uint2 v = __ldg(xh2 + (size_t)s * 16 + q);
                float2 f0 = __half22float2(*(__half2*)&v.x);
                float2 f1 = __half22float2(*(__half2*)&v.y);
                a0 += f0.x; a1 += f0.y; a2 += f1.x; a3 += f1.y;
            }
        }
    }
    for (; j < maxdg; j++) {
        if (j < dg) {
            int s = __ldg(csr + base + j);
            uint2 v = __ldg(xh2 + (size_t)s * 16 + q);
            float2 f0 = __half22float2(*(__half2*)&v.x);
            float2 f1 = __half22float2(*(__half2*)&v.y);
            a0 += f0.x; a1 += f0.y; a2 += f1.x; a3 += f1.y;
        }
    }

    float inv = 1.0f / fmaxf((float)dg, 1.0f);
    if (valid)
        mean4[(size_t)node * 16 + q] =
            make_float4(a0 * inv, a1 * inv, a2 * inv, a3 * inv);
}

// ---------------- combine: out = mean@Wl^T + b + x@Wr^T (+ReLU) ------------
// 256 threads, TILE=64 nodes/block -> 65KB smem -> 3 blocks/SM.
// Thread: fq = tid&15 (4 features), g = tid>>4 (node pairs g and g+16).
__global__ void __launch_bounds__(256)
combine_kernel(const float* __restrict__ xin,
               const float* __restrict__ mean,
               const float* __restrict__ Wl,
               const float* __restrict__ bl,
               const float* __restrict__ Wr,
               float* __restrict__ out,
               __half* __restrict__ out_h,
               int n_nodes, int do_relu) {
    extern __shared__ float sm[];
    float* wlT = sm;                 // [64][64] wlT[k*64+f]
    float* wrT = wlT + D * D;
    float* xsT = wrT + D * D;        // [64][RS] k-major, 64 nodes
    float* msT = xsT + D * RS;

    int tid = threadIdx.x;
    for (int i = tid; i < D * D; i += 256) {
        int f = i >> 6, k = i & 63;
        wlT[k * D + f] = Wl[i];
        wrT[k * D + f] = Wr[i];
    }
    int nb = blockIdx.x * TILE;
    // stage 64 nodes x 16 quads = 1024 slots, 4 iters
    for (int i = tid; i < TILE * 16; i += 256) {
        int n = i & (TILE - 1);
        int k4 = (i >> 6) * 4;
        int gn = nb + n;
        float4 xv = make_float4(0.f, 0.f, 0.f, 0.f);
        float4 mv = make_float4(0.f, 0.f, 0.f, 0.f);
        if (gn < n_nodes) {
            xv = __ldg((const float4*)(xin + (size_t)gn * D + k4));
            mv = __ldg((const float4*)(mean + (size_t)gn * D + k4));
        }
        xsT[(k4 + 0) * RS + n] = xv.x;
        xsT[(k4 + 1) * RS + n] = xv.y;
        xsT[(k4 + 2) * RS + n] = xv.z;
        xsT[(k4 + 3) * RS + n] = xv.w;
        msT[(k4 + 0) * RS + n] = mv.x;
        msT[(k4 + 1) * RS + n] = mv.y;
        msT[(k4 + 2) * RS + n] = mv.z;
        msT[(k4 + 3) * RS + n] = mv.w;
    }
    __syncthreads();

    int fq = tid & 15;
    int g = tid >> 4;

    float4 b4 = __ldg((const float4*)(bl + fq * 4));
    u64 acc[2][4];
    {
        u64 bp0 = pack2(b4.x), bp1 = pack2(b4.y), bp2 = pack2(b4.z), bp3 = pack2(b4.w);
#pragma unroll
        for (int p = 0; p < 2; p++) {
            acc[p][0] = bp0; acc[p][1] = bp1; acc[p][2] = bp2; acc[p][3] = bp3;
        }
    }

    const float4* wl4 = (const float4*)wlT;
    const float4* wr4 = (const float4*)wrT;
    const u64* msv = (const u64*)msT;    // RS64 u64 per k-row
    const u64* xsv = (const u64*)xsT;

#pragma unroll 4
    for (int k = 0; k < D; k++) {
        float4 wl = wl4[k * 16 + fq];
        float4 wr = wr4[k * 16 + fq];
        u64 wl2[4] = {pack2(wl.x), pack2(wl.y), pack2(wl.z), pack2(wl.w)};
        u64 wr2[4] = {pack2(wr.x), pack2(wr.y), pack2(wr.z), pack2(wr.w)};
        u64 m0 = msv[k * RS64 + g];          // nodes 2g, 2g+1
        u64 m1 = msv[k * RS64 + 16 + g];     // nodes 32+2g, 33+2g
        u64 x0 = xsv[k * RS64 + g];
        u64 x1 = xsv[k * RS64 + 16 + g];
#pragma unroll
        for (int f = 0; f < 4; f++) {
            acc[0][f] = fma2(m0, wl2[f], acc[0][f]);
            acc[0][f] = fma2(x0, wr2[f], acc[0][f]);
            acc[1][f] = fma2(m1, wl2[f], acc[1][f]);
            acc[1][f] = fma2(x1, wr2[f], acc[1][f]);
        }
    }

#pragma unroll
    for (int p = 0; p < 2; p++) {
        int nlo = 2 * g + 32 * p;
        float lo[4], hi[4];
#pragma unroll
        for (int f = 0; f < 4; f++) unpack2(acc[p][f], lo[f], hi[f]);
        if (do_relu) {
#pragma unroll
            for (int f = 0; f < 4; f++) {
                lo[f] = fmaxf(lo[f], 0.f);
                hi[f] = fmaxf(hi[f], 0.f);
            }
        }
        int gn0 = nb + nlo;
        int gn1 = gn0 + 1;
        if (gn0 < n_nodes) {
            *(float4*)(out + (size_t)gn0 * D + fq * 4) =
                make_float4(lo[0], lo[1], lo[2], lo[3]);
            if (out_h) {
                __half2 h0 = __floats2half2_rn(lo[0], lo[1]);
                __half2 h1 = __floats2half2_rn(lo[2], lo[3]);
                uint2 o;
                o.x = *(unsigned*)&h0;
                o.y = *(unsigned*)&h1;
                *(uint2*)(out_h + (size_t)gn0 * D + fq * 4) = o;
            }
        }
        if (gn1 < n_nodes) {
            *(float4*)(out + (size_t)gn1 * D + fq * 4) =
                make_float4(hi[0], hi[1], hi[2], hi[3]);
            if (out_h) {
                __half2 h0 = __floats2half2_rn(hi[0], hi[1]);
                __half2 h1 = __floats2half2_rn(hi[2], hi[3]);
                uint2 o;
                o.x = *(unsigned*)&h0;
                o.y = *(unsigned*)&h1;
                *(uint2*)(out_h + (size_t)gn1 * D + fq * 4) = o;
            }
        }
    }
}

// ---------------------------------------------------------------------------
extern "C" void kernel_launch(void* const* d_in, const int* in_sizes, int n_in,
                              void* d_out, int out_size) {
    const float* x   = (const float*)d_in[0];
    const int*   ei  = (const int*)  d_in[1];
    const float* W1l = (const float*)d_in[2];
    const float* b1l = (const float*)d_in[3];
    const float* W1r = (const float*)d_in[4];
    const float* W2l = (const float*)d_in[5];
    const float* b2l = (const float*)d_in[6];
    const float* W2r = (const float*)d_in[7];
    float* out = (float*)d_out;

    int n_nodes = in_sizes[0] / D;
    int n_edges = in_sizes[1] / 2;
    const int* src = ei;
    const int* dst = ei + n_edges;

    float *mean, *h;
    __half* xh;
    int *deg, *rowptr, *cursor, *csr, *bsums, *boffs;
    cudaGetSymbolAddress((void**)&mean,   g_mean);
    cudaGetSymbolAddress((void**)&h,      g_h);
    cudaGetSymbolAddress((void**)&xh,     g_xh);
    cudaGetSymbolAddress((void**)&deg,    g_deg);
    cudaGetSymbolAddress((void**)&rowptr, g_rowptr);
    cudaGetSymbolAddress((void**)&cursor, g_cursor);
    cudaGetSymbolAddress((void**)&csr,    g_csrsrc);
    cudaGetSymbolAddress((void**)&bsums,  g_blocksums);
    cudaGetSymbolAddress((void**)&boffs,  g_blockoffs);

    const int SMEM = (2 * D * D + 2 * D * RS) * (int)sizeof(float); // 65 KB
    cudaFuncSetAttribute(combine_kernel,
                         cudaFuncAttributeMaxDynamicSharedMemorySize, SMEM);
    cudaFuncSetAttribute(combine_kernel,
                         cudaFuncAttributePreferredSharedMemoryCarveout, 100);

    int eblocks = (n_edges + 255) / 256;
    int nscan = (n_nodes + 1023) / 1024;
    int nblocks = (n_nodes + 255) / 256;
    int npairs = (n_nodes + 1) / 2;
    int ablocks = (npairs * 32 + 255) / 256;
    int cblocks = (n_nodes + TILE - 1) / TILE;
    int n4 = n_nodes * D / 4;
    int vblocks = (n4 + 255) / 256;

    // ---- CSR build + x fp16 conversion ----
    cudaMemsetAsync(deg, 0, (size_t)n_nodes * sizeof(int));
    convert_kernel<<<vblocks, 256>>>((const float4*)x, (uint2*)xh, n4);
    count_kernel<<<eblocks, 256>>>(dst, deg, n_edges);
    scan_kernel<<<nscan, 1024>>>(deg, rowptr, bsums, n_nodes);
    scan_kernel<<<1, 1024>>>(bsums, boffs, nullptr, nscan);
    add_off_kernel<<<nblocks, 256>>>(rowptr, cursor, boffs, n_nodes);
    fill_kernel<<<eblocks, 256>>>(src, dst, cursor, csr, n_edges);

    // ---- Layer 1 ----
    aggregate_kernel<<<ablocks, 256>>>((const uint2*)xh, csr, rowptr, deg,
                                       (float4*)mean, n_nodes);
    combine_kernel<<<cblocks, 256, SMEM>>>(x, mean, W1l, b1l, W1r, h, xh,
                                           n_nodes, 1);   // xh now holds h16

    // ---- Layer 2 ----
    aggregate_kernel<<<ablocks, 256>>>((const uint2*)xh, csr, rowptr, deg,
                                       (float4*)mean, n_nodes);
    combine_kernel<<<cblocks, 256, SMEM>>>(h, mean, W2l, b2l, W2r, out, nullptr,
                                           n_nodes, 0);
}

// round 8
// speedup vs baseline: 1.2199x; 1.2199x over previous
#include <cuda_runtime.h>
#include <cuda_fp16.h>

#define D 64
#define MAXN 100000
#define MAXE 1600000
#define TILE 128

typedef unsigned long long u64;

// ---------------- static scratch (no allocation allowed) -------------------
__device__ float  g_mean[(size_t)MAXN * D];
__device__ float  g_h[(size_t)MAXN * D];
__device__ __half g_xh[(size_t)MAXN * D];      // fp16 copy of gather operand
__device__ int    g_deg[MAXN];
__device__ int    g_rowptr[MAXN];
__device__ int    g_cursor[MAXN];
__device__ int    g_csrsrc[MAXE + 3 * MAXN + 8];  // rows padded to 4-int align
__device__ int    g_blocksums[128];

// ---------------- f32x2 helpers --------------------------------------------
__device__ __forceinline__ u64 fma2(u64 a, u64 b, u64 c) {
    u64 d;
    asm("fma.rn.f32x2 %0, %1, %2, %3;" : "=l"(d) : "l"(a), "l"(b), "l"(c));
    return d;
}
__device__ __forceinline__ u64 pack2(float v) {
    u64 d;
    asm("mov.b64 %0, {%1, %1};" : "=l"(d) : "f"(v));
    return d;
}
__device__ __forceinline__ void unpack2(u64 v, float& lo, float& hi) {
    asm("mov.b64 {%0, %1}, %2;" : "=f"(lo), "=f"(hi) : "l"(v));
}

// ---------------- CSR build ------------------------------------------------
__global__ void count_kernel(const int* __restrict__ dst, int* __restrict__ deg,
                             int n_edges) {
    int e = blockIdx.x * blockDim.x + threadIdx.x;
    if (e < n_edges) atomicAdd(deg + __ldg(dst + e), 1);
}

// Exclusive scan of ceil4(deg) over 1024-element chunks.
__global__ void scan_kernel(const int* __restrict__ in, int* __restrict__ out,
                            int* sums, int n) {
    __shared__ int sm[1024];
    int t = threadIdx.x;
    int i = blockIdx.x * 1024 + t;
    int v = (i < n) ? ((in[i] + 3) & ~3) : 0;   // padded degree
    sm[t] = v;
    __syncthreads();
#pragma unroll
    for (int off = 1; off < 1024; off <<= 1) {
        int add = (t >= off) ? sm[t - off] : 0;
        __syncthreads();
        sm[t] += add;
        __syncthreads();
    }
    if (i < n) out[i] = sm[t] - v;            // exclusive
    if (sums != nullptr && t == 1023) sums[blockIdx.x] = sm[1023];
}

// Fused: scan the (<=128) chunk sums in smem, then add offsets.
__global__ void add_off_kernel(int* __restrict__ rowptr, int* __restrict__ cursor,
                               const int* __restrict__ bsums, int nscan, int n) {
    __shared__ int sb[128];
    __shared__ int sorig[128];
    int t = threadIdx.x;
    if (t < 128) {
        int v = (t < nscan) ? bsums[t] : 0;
        sb[t] = v;
        sorig[t] = v;
    }
    __syncthreads();
#pragma unroll
    for (int off = 1; off < 128; off <<= 1) {
        int add = 0;
        if (t < 128 && t >= off) add = sb[t - off];
        __syncthreads();
        if (t < 128) sb[t] += add;
        __syncthreads();
    }
    int i = blockIdx.x * blockDim.x + t;
    if (i < n) {
        int c = i >> 10;
        int v = rowptr[i] + sb[c] - sorig[c];   // + exclusive chunk offset
        rowptr[i] = v;
        cursor[i] = v;
    }
}

__global__ void fill_kernel(const int* __restrict__ src, const int* __restrict__ dst,
                            int* __restrict__ cursor, int* __restrict__ csr,
                            int n_edges) {
    int e = blockIdx.x * blockDim.x + threadIdx.x;
    if (e < n_edges) {
        int d = __ldg(dst + e);
        int pos = atomicAdd(cursor + d, 1);
        csr[pos] = __ldg(src + e);
    }
}

// ---------------- fp32 -> fp16 conversion (x only) --------------------------
__global__ void convert_kernel(const float4* __restrict__ in,
                               uint2* __restrict__ outh, int n4) {
    int i = blockIdx.x * blockDim.x + threadIdx.x;
    if (i < n4) {
        float4 v = __ldg(in + i);
        __half2 h0 = __floats2half2_rn(v.x, v.y);
        __half2 h1 = __floats2half2_rn(v.z, v.w);
        uint2 o;
        o.x = *(unsigned*)&h0;
        o.y = *(unsigned*)&h1;
        outh[i] = o;
    }
}

// ---------------- aggregate: mean of in-neighbors (fp16 gather) -------------
// 2 nodes/warp: lanes 0-15 node 2w, lanes 16-31 node 2w+1.
// Rows are 16B-aligned in csr, so 8 indices load as 2 x LDG.128.
__global__ void aggregate_kernel(const uint2* __restrict__ xh2,
                                 const int* __restrict__ csr,
                                 const int* __restrict__ rowptr,
                                 const int* __restrict__ deg,
                                 float4* __restrict__ mean4, int n_nodes) {
    int warp = (blockIdx.x * blockDim.x + threadIdx.x) >> 5;
    int n0 = warp * 2;
    if (n0 >= n_nodes) return;
    int lane = threadIdx.x & 31;
    int half = lane >> 4;
    int q = lane & 15;                 // halves 4q..4q+3 of the row
    int node = n0 + half;
    bool valid = node < n_nodes;

    int base = valid ? __ldg(rowptr + node) : 0;
    int dg   = valid ? __ldg(deg + node) : 0;
    int dgA = __shfl_sync(0xffffffffu, dg, 0);
    int dgB = __shfl_sync(0xffffffffu, dg, 16);
    int maxdg = max(dgA, dgB);

    float a0 = 0.f, a1 = 0.f, a2 = 0.f, a3 = 0.f;

    int j = 0;
    for (; j + 8 <= maxdg; j += 8) {
        int4 i0 = __ldg((const int4*)(csr + base + j));
        int4 i1 = __ldg((const int4*)(csr + base + j + 4));
        int idx[8] = {i0.x, i0.y, i0.z, i0.w, i1.x, i1.y, i1.z, i1.w};
#pragma unroll
        for (int i = 0; i < 8; i++) {
            if (j + i < dg) {
                uint2 v = __ldg(xh2 + (size_t)idx[i] * 16 + q);
                float2 f0 = __half22float2(*(__half2*)&v.x);
                float2 f1 = __half22float2(*(__half2*)&v.y);
                a0 += f0.x; a1 += f0.y; a2 += f1.x; a3 += f1.y;
            }
        }
    }
    for (; j < maxdg; j += 4) {
        int4 i0 = __ldg((const int4*)(csr + base + j));   // in-bounds (padded)
        int idx[4] = {i0.x, i0.y, i0.z, i0.w};
#pragma unroll
        for (int i = 0; i < 4; i++) {
            if (j + i < dg) {
                uint2 v = __ldg(xh2 + (size_t)idx[i] * 16 + q);
                float2 f0 = __half22float2(*(__half2*)&v.x);
                float2 f1 = __half22float2(*(__half2*)&v.y);
                a0 += f0.x; a1 += f0.y; a2 += f1.x; a3 += f1.y;
            }
        }
    }

    float inv = 1.0f / fmaxf((float)dg, 1.0f);
    if (valid)
        mean4[(size_t)node * 16 + q] =
            make_float4(a0 * inv, a1 * inv, a2 * inv, a3 * inv);
}

// ---------------- combine (R6 version): out = mean@Wl^T + b + x@Wr^T -------
__global__ void combine_kernel(const float* __restrict__ xin,
                               const float* __restrict__ mean,
                               const float* __restrict__ Wl,
                               const float* __restrict__ bl,
                               const float* __restrict__ Wr,
                               float* __restrict__ out,
                               __half* __restrict__ out_h,
                               int n_nodes, int do_relu) {
    extern __shared__ float sm[];
    float* wlT = sm;                 // [64][64] wlT[k*64+f]
    float* wrT = wlT + D * D;
    float* xsT = wrT + D * D;        // [64][128] k-major
    float* msT = xsT + D * TILE;

    int tid = threadIdx.x;
    for (int i = tid; i < D * D; i += 256) {
        int f = i >> 6, k = i & 63;
        wlT[k * D + f] = Wl[i];
        wrT[k * D + f] = Wr[i];
    }
    int nb = blockIdx.x * TILE;
    for (int i = tid; i < TILE * 16; i += 256) {
        int n = i & (TILE - 1);
        int k4 = (i >> 7) * 4;
        int gn = nb + n;
        float4 xv = make_float4(0.f, 0.f, 0.f, 0.f);
        float4 mv = make_float4(0.f, 0.f, 0.f, 0.f);
        if (gn < n_nodes) {
            xv = __ldg((const float4*)(xin + (size_t)gn * D + k4));
            mv = __ldg((const float4*)(mean + (size_t)gn * D + k4));
        }
        xsT[(k4 + 0) * TILE + n] = xv.x;
        xsT[(k4 + 1) * TILE + n] = xv.y;
        xsT[(k4 + 2) * TILE + n] = xv.z;
        xsT[(k4 + 3) * TILE + n] = xv.w;
        msT[(k4 + 0) * TILE + n] = mv.x;
        msT[(k4 + 1) * TILE + n] = mv.y;
        msT[(k4 + 2) * TILE + n] = mv.z;
        msT[(k4 + 3) * TILE + n] = mv.w;
    }
    __syncthreads();

    int fq = tid & 15;
    int g = tid >> 4;

    float4 b4 = __ldg((const float4*)(bl + fq * 4));
    u64 acc[4][4];
    {
        u64 bp0 = pack2(b4.x), bp1 = pack2(b4.y), bp2 = pack2(b4.z), bp3 = pack2(b4.w);
#pragma unroll
        for (int p = 0; p < 4; p++) {
            acc[p][0] = bp0; acc[p][1] = bp1; acc[p][2] = bp2; acc[p][3] = bp3;
        }
    }

    const float4* wl4 = (const float4*)wlT;
    const float4* wr4 = (const float4*)wrT;
    const ulonglong2* msv = (const ulonglong2*)msT;
    const ulonglong2* xsv = (const ulonglong2*)xsT;

#pragma unroll 4
    for (int k = 0; k < D; k++) {
        float4 wl = wl4[k * 16 + fq];
        float4 wr = wr4[k * 16 + fq];
        u64 wl2[4] = {pack2(wl.x), pack2(wl.y), pack2(wl.z), pack2(wl.w)};
        u64 wr2[4] = {pack2(wr.x), pack2(wr.y), pack2(wr.z), pack2(wr.w)};
        ulonglong2 m01 = msv[k * 32 + g];
        ulonglong2 m23 = msv[k * 32 + 16 + g];
        ulonglong2 x01 = xsv[k * 32 + g];
        ulonglong2 x23 = xsv[k * 32 + 16 + g];
#pragma unroll
        for (int f = 0; f < 4; f++) {
            acc[0][f] = fma2(m01.x, wl2[f], acc[0][f]);
            acc[0][f] = fma2(x01.x, wr2[f], acc[0][f]);
            acc[1][f] = fma2(m01.y, wl2[f], acc[1][f]);
            acc[1][f] = fma2(x01.y, wr2[f], acc[1][f]);
            acc[2][f] = fma2(m23.x, wl2[f], acc[2][f]);
            acc[2][f] = fma2(x23.x, wr2[f], acc[2][f]);
            acc[3][f] = fma2(m23.y, wl2[f], acc[3][f]);
            acc[3][f] = fma2(x23.y, wr2[f], acc[3][f]);
        }
    }

#pragma unroll
    for (int p = 0; p < 4; p++) {
        int nlo = (p < 2) ? (4 * g + 2 * p) : (64 + 4 * g + 2 * (p - 2));
        float lo[4], hi[4];
#pragma unroll
        for (int f = 0; f < 4; f++) unpack2(acc[p][f], lo[f], hi[f]);
        if (do_relu) {
#pragma unroll
            for (int f = 0; f < 4; f++) {
                lo[f] = fmaxf(lo[f], 0.f);
                hi[f] = fmaxf(hi[f], 0.f);
            }
        }
        int gn0 = nb + nlo;
        int gn1 = gn0 + 1;
        if (gn0 < n_nodes) {
            *(float4*)(out + (size_t)gn0 * D + fq * 4) =
                make_float4(lo[0], lo[1], lo[2], lo[3]);
            if (out_h) {
                __half2 h0 = __floats2half2_rn(lo[0], lo[1]);
                __half2 h1 = __floats2half2_rn(lo[2], lo[3]);
                uint2 o;
                o.x = *(unsigned*)&h0;
                o.y = *(unsigned*)&h1;
                *(uint2*)(out_h + (size_t)gn0 * D + fq * 4) = o;
            }
        }
        if (gn1 < n_nodes) {
            *(float4*)(out + (size_t)gn1 * D + fq * 4) =
                make_float4(hi[0], hi[1], hi[2], hi[3]);
            if (out_h) {
                __half2 h0 = __floats2half2_rn(hi[0], hi[1]);
                __half2 h1 = __floats2half2_rn(hi[2], hi[3]);
                uint2 o;
                o.x = *(unsigned*)&h0;
                o.y = *(unsigned*)&h1;
                *(uint2*)(out_h + (size_t)gn1 * D + fq * 4) = o;
            }
        }
    }
}

// ---------------------------------------------------------------------------
extern "C" void kernel_launch(void* const* d_in, const int* in_sizes, int n_in,
                              void* d_out, int out_size) {
    const float* x   = (const float*)d_in[0];
    const int*   ei  = (const int*)  d_in[1];
    const float* W1l = (const float*)d_in[2];
    const float* b1l = (const float*)d_in[3];
    const float* W1r = (const float*)d_in[4];
    const float* W2l = (const float*)d_in[5];
    const float* b2l = (const float*)d_in[6];
    const float* W2r = (const float*)d_in[7];
    float* out = (float*)d_out;

    int n_nodes = in_sizes[0] / D;
    int n_edges = in_sizes[1] / 2;
    const int* src = ei;
    const int* dst = ei + n_edges;

    float *mean, *h;
    __half* xh;
    int *deg, *rowptr, *cursor, *csr, *bsums;
    cudaGetSymbolAddress((void**)&mean,   g_mean);
    cudaGetSymbolAddress((void**)&h,      g_h);
    cudaGetSymbolAddress((void**)&xh,     g_xh);
    cudaGetSymbolAddress((void**)&deg,    g_deg);
    cudaGetSymbolAddress((void**)&rowptr, g_rowptr);
    cudaGetSymbolAddress((void**)&cursor, g_cursor);
    cudaGetSymbolAddress((void**)&csr,    g_csrsrc);
    cudaGetSymbolAddress((void**)&bsums,  g_blocksums);

    const int SMEM = (2 * D * D + 2 * D * TILE) * (int)sizeof(float); // 96 KB
    cudaFuncSetAttribute(combine_kernel,
                         cudaFuncAttributeMaxDynamicSharedMemorySize, SMEM);

    int eblocks = (n_edges + 255) / 256;
    int nscan = (n_nodes + 1023) / 1024;
    int nblocks = (n_nodes + 255) / 256;
    int npairs = (n_nodes + 1) / 2;
    int ablocks = (npairs * 32 + 255) / 256;
    int cblocks = (n_nodes + TILE - 1) / TILE;
    int n4 = n_nodes * D / 4;
    int vblocks = (n4 + 255) / 256;

    // ---- CSR build (rows padded to 16B) + x fp16 conversion ----
    cudaMemsetAsync(deg, 0, (size_t)n_nodes * sizeof(int));
    convert_kernel<<<vblocks, 256>>>((const float4*)x, (uint2*)xh, n4);
    count_kernel<<<eblocks, 256>>>(dst, deg, n_edges);
    scan_kernel<<<nscan, 1024>>>(deg, rowptr, bsums, n_nodes);
    add_off_kernel<<<nblocks, 256>>>(rowptr, cursor, bsums, nscan, n_nodes);
    fill_kernel<<<eblocks, 256>>>(src, dst, cursor, csr, n_edges);

    // ---- Layer 1 ----
    aggregate_kernel<<<ablocks, 256>>>((const uint2*)xh, csr, rowptr, deg,
                                       (float4*)mean, n_nodes);
    combine_kernel<<<cblocks, 256, SMEM>>>(x, mean, W1l, b1l, W1r, h, xh,
                                           n_nodes, 1);   // xh now holds h16

    // ---- Layer 2 ----
    aggregate_kernel<<<ablocks, 256>>>((const uint2*)xh, csr, rowptr, deg,
                                       (float4*)mean, n_nodes);
    combine_kernel<<<cblocks, 256, SMEM>>>(h, mean, W2l, b2l, W2r, out, nullptr,
                                           n_nodes, 0);
}

// round 10
// speedup vs baseline: 1.5738x; 1.2901x over previous
#include <cuda_runtime.h>
#include <cuda_fp16.h>
#include <mma.h>
#include <cstdint>

using namespace nvcuda;

#define D 64
#define MAXN 100000
#define MAXNP 100096           // padded so last tile's wmma A-loads stay in-bounds
#define MAXE 1600000
#define TILE 128
#define EPI_LD 68              // epilogue smem row stride (floats)

// ---------------- static scratch (no allocation allowed) -------------------
__device__ __half g_meanh[(size_t)MAXNP * D];
__device__ __half g_meanl[(size_t)MAXNP * D];
__device__ __half g_xh[(size_t)MAXNP * D];    // hi of gather/self operand
__device__ __half g_xl[(size_t)MAXNP * D];    // lo residual
__device__ __half g_w16[2 * 4 * 4096];        // per layer: wl_hi, wl_lo, wr_hi, wr_lo
__device__ int    g_deg[MAXN];
__device__ int    g_rowptr[MAXN];
__device__ int    g_cursor[MAXN];
__device__ int    g_csrsrc[MAXE];
__device__ int    g_blocksums[128];
__device__ int    g_blockoffs[128];

// ---------------- CSR build (R6 version) ------------------------------------
__global__ void count_kernel(const int* __restrict__ dst, int* __restrict__ deg,
                             int n_edges) {
    int e = blockIdx.x * blockDim.x + threadIdx.x;
    if (e < n_edges) atomicAdd(deg + __ldg(dst + e), 1);
}

__global__ void scan_kernel(const int* __restrict__ in, int* __restrict__ out,
                            int* sums, int n) {
    __shared__ int sm[1024];
    int t = threadIdx.x;
    int i = blockIdx.x * 1024 + t;
    int v = (i < n) ? in[i] : 0;
    sm[t] = v;
    __syncthreads();
#pragma unroll
    for (int off = 1; off < 1024; off <<= 1) {
        int add = (t >= off) ? sm[t - off] : 0;
        __syncthreads();
        sm[t] += add;
        __syncthreads();
    }
    if (i < n) out[i] = sm[t] - v;
    if (sums != nullptr && t == 1023) sums[blockIdx.x] = sm[1023];
}

__global__ void add_off_kernel(int* __restrict__ rowptr, int* __restrict__ cursor,
                               const int* __restrict__ boffs, int n) {
    int i = blockIdx.x * blockDim.x + threadIdx.x;
    if (i < n) {
        int v = rowptr[i] + boffs[i >> 10];
        rowptr[i] = v;
        cursor[i] = v;
    }
}

__global__ void fill_kernel(const int* __restrict__ src, const int* __restrict__ dst,
                            int* __restrict__ cursor, int* __restrict__ csr,
                            int n_edges) {
    int e = blockIdx.x * blockDim.x + threadIdx.x;
    if (e < n_edges) {
        int d = __ldg(dst + e);
        int pos = atomicAdd(cursor + d, 1);
        csr[pos] = __ldg(src + e);
    }
}

// ---------------- fp32 -> fp16 hi/lo conversion (x) --------------------------
__global__ void convert_kernel(const float4* __restrict__ in,
                               uint2* __restrict__ outh,
                               uint2* __restrict__ outl, int n4) {
    int i = blockIdx.x * blockDim.x + threadIdx.x;
    if (i < n4) {
        float4 v = __ldg(in + i);
        __half2 h0 = __floats2half2_rn(v.x, v.y);
        __half2 h1 = __floats2half2_rn(v.z, v.w);
        float2 f0 = __half22float2(h0);
        float2 f1 = __half22float2(h1);
        __half2 l0 = __floats2half2_rn(v.x - f0.x, v.y - f0.y);
        __half2 l1 = __floats2half2_rn(v.z - f1.x, v.w - f1.y);
        outh[i] = make_uint2(*(unsigned*)&h0, *(unsigned*)&h1);
        outl[i] = make_uint2(*(unsigned*)&l0, *(unsigned*)&l1);
    }
}

// ---------------- weight hi/lo split (both layers) ---------------------------
__global__ void wsplit_kernel(const float* __restrict__ W1l,
                              const float* __restrict__ W1r,
                              const float* __restrict__ W2l,
                              const float* __restrict__ W2r,
                              __half* __restrict__ w16) {
    int i = blockIdx.x * blockDim.x + threadIdx.x;
    if (i >= 4096) return;
    const float* srcs[4] = {W1l, W1r, W2l, W2r};
#pragma unroll
    for (int l = 0; l < 2; l++) {
#pragma unroll
        for (int m = 0; m < 2; m++) {
            float v = __ldg(srcs[l * 2 + m] + i);
            __half hi = __float2half_rn(v);
            __half lo = __float2half_rn(v - __half2float(hi));
            w16[((size_t)l * 4 + m * 2 + 0) * 4096 + i] = hi;
            w16[((size_t)l * 4 + m * 2 + 1) * 4096 + i] = lo;
        }
    }
}

// ---------------- aggregate (R6 gather): fp16 gather, fp32 sum, hi/lo out ---
__global__ void aggregate_kernel(const uint2* __restrict__ xh2,
                                 const int* __restrict__ csr,
                                 const int* __restrict__ rowptr,
                                 const int* __restrict__ deg,
                                 __half* __restrict__ mh,
                                 __half* __restrict__ ml, int n_nodes) {
    int warp = (blockIdx.x * blockDim.x + threadIdx.x) >> 5;
    int n0 = warp * 2;
    if (n0 >= n_nodes) return;
    int lane = threadIdx.x & 31;
    int half_ = lane >> 4;
    int q = lane & 15;
    int node = n0 + half_;
    bool valid = node < n_nodes;

    int base = valid ? __ldg(rowptr + node) : 0;
    int dg   = valid ? __ldg(deg + node) : 0;
    int dgA = __shfl_sync(0xffffffffu, dg, 0);
    int dgB = __shfl_sync(0xffffffffu, dg, 16);
    int maxdg = max(dgA, dgB);

    float a0 = 0.f, a1 = 0.f, a2 = 0.f, a3 = 0.f;

    int j = 0;
    for (; j + 8 <= maxdg; j += 8) {
#pragma unroll
        for (int i = 0; i < 8; i++) {
            if (j + i < dg) {
                int s = __ldg(csr + base + j + i);
                uint2 v = __ldg(xh2 + (size_t)s * 16 + q);
                float2 f0 = __half22float2(*(__half2*)&v.x);
                float2 f1 = __half22float2(*(__half2*)&v.y);
                a0 += f0.x; a1 += f0.y; a2 += f1.x; a3 += f1.y;
            }
        }
    }
    for (; j < maxdg; j++) {
        if (j < dg) {
            int s = __ldg(csr + base + j);
            uint2 v = __ldg(xh2 + (size_t)s * 16 + q);
            float2 f0 = __half22float2(*(__half2*)&v.x);
            float2 f1 = __half22float2(*(__half2*)&v.y);
            a0 += f0.x; a1 += f0.y; a2 += f1.x; a3 += f1.y;
        }
    }

    float inv = 1.0f / fmaxf((float)dg, 1.0f);
    a0 *= inv; a1 *= inv; a2 *= inv; a3 *= inv;
    if (valid) {
        __half2 h0 = __floats2half2_rn(a0, a1);
        __half2 h1 = __floats2half2_rn(a2, a3);
        float2 f0 = __half22float2(h0);
        float2 f1 = __half22float2(h1);
        __half2 l0 = __floats2half2_rn(a0 - f0.x, a1 - f0.y);
        __half2 l1 = __floats2half2_rn(a2 - f1.x, a3 - f1.y);
        *(uint2*)(mh + (size_t)node * D + q * 4) =
            make_uint2(*(unsigned*)&h0, *(unsigned*)&h1);
        *(uint2*)(ml + (size_t)node * D + q * 4) =
            make_uint2(*(unsigned*)&l0, *(unsigned*)&l1);
    }
}

// ---------------- combine via wmma HMMA --------------------------------------
// out = mean@Wl^T + b + self@Wr^T, split-fp16: Ah*Wh + Al*Wh + Ah*Wl per GEMM.
// 128 threads; warp w computes rows [nb+32w, nb+32w+32) x all 64 cols.
__global__ void __launch_bounds__(128)
combine_wmma(const __half* __restrict__ mh, const __half* __restrict__ ml,
             const __half* __restrict__ ah, const __half* __restrict__ al,
             const __half* __restrict__ w,     // wl_hi, wl_lo, wr_hi, wr_lo
             const float* __restrict__ bias,
             float* __restrict__ out32,        // layer 2 final (or null)
             __half* __restrict__ oh,          // layer 1 hi out (or null)
             __half* __restrict__ ol,          // layer 1 lo out (or null)
             int n_nodes, int do_relu) {
    extern __shared__ float epi[];            // [4][32][EPI_LD]
    int tid = threadIdx.x, wid = tid >> 5, lane = tid & 31;
    int rbase = blockIdx.x * TILE + wid * 32;

    wmma::fragment<wmma::accumulator, 16, 16, 16, float> acc[2][4];
#pragma unroll
    for (int mt = 0; mt < 2; mt++)
#pragma unroll
        for (int nt = 0; nt < 4; nt++) wmma::fill_fragment(acc[mt][nt], 0.0f);

#pragma unroll
    for (int k = 0; k < D; k += 16) {
        wmma::fragment<wmma::matrix_a, 16, 16, 16, __half, wmma::row_major>
            fmh[2], fml[2], fah[2], fal[2];
#pragma unroll
        for (int mt = 0; mt < 2; mt++) {
            size_t ab = (size_t)(rbase + mt * 16) * D + k;
            wmma::load_matrix_sync(fmh[mt], mh + ab, D);
            wmma::load_matrix_sync(fml[mt], ml + ab, D);
            wmma::load_matrix_sync(fah[mt], ah + ab, D);
            wmma::load_matrix_sync(fal[mt], al + ab, D);
        }
#pragma unroll
        for (int nt = 0; nt < 4; nt++) {
            // B[k][n] = W[n][k]; row-major W + col_major fragment = W^T
            size_t wb = (size_t)(nt * 16) * D + k;
            wmma::fragment<wmma::matrix_b, 16, 16, 16, __half, wmma::col_major>
                bwlh, bwll, bwrh, bwrl;
            wmma::load_matrix_sync(bwlh, w + 0 * 4096 + wb, D);
            wmma::load_matrix_sync(bwll, w + 1 * 4096 + wb, D);
            wmma::load_matrix_sync(bwrh, w + 2 * 4096 + wb, D);
            wmma::load_matrix_sync(bwrl, w + 3 * 4096 + wb, D);
#pragma unroll
            for (int mt = 0; mt < 2; mt++) {
                wmma::mma_sync(acc[mt][nt], fmh[mt], bwlh, acc[mt][nt]);
                wmma::mma_sync(acc[mt][nt], fml[mt], bwlh, acc[mt][nt]);
                wmma::mma_sync(acc[mt][nt], fmh[mt], bwll, acc[mt][nt]);
                wmma::mma_sync(acc[mt][nt], fah[mt], bwrh, acc[mt][nt]);
                wmma::mma_sync(acc[mt][nt], fal[mt], bwrh, acc[mt][nt]);
                wmma::mma_sync(acc[mt][nt], fah[mt], bwrl, acc[mt][nt]);
            }
        }
    }

    // epilogue: acc -> smem -> bias + relu -> coalesced stores
    float* ws = epi + (size_t)wid * 32 * EPI_LD;
#pragma unroll
    for (int mt = 0; mt < 2; mt++)
#pragma unroll
        for (int nt = 0; nt < 4; nt++)
            wmma::store_matrix_sync(ws + mt * 16 * EPI_LD + nt * 16,
                                    acc[mt][nt], EPI_LD, wmma::mem_row_major);
    __syncwarp();

    int q = lane & 15;                  // column quad
    int rh = lane >> 4;                 // row parity
    float4 b4 = __ldg((const float4*)bias + q);
#pragma unroll
    for (int it = 0; it < 16; it++) {
        int r = it * 2 + rh;
        float4 v = *(float4*)(ws + r * EPI_LD + q * 4);
        v.x += b4.x; v.y += b4.y; v.z += b4.z; v.w += b4.w;
        if (do_relu) {
            v.x = fmaxf(v.x, 0.f); v.y = fmaxf(v.y, 0.f);
            v.z = fmaxf(v.z, 0.f); v.w = fmaxf(v.w, 0.f);
        }
        int gm = rbase + r;
        if (gm < n_nodes) {
            if (out32) *(float4*)(out32 + (size_t)gm * D + q * 4) = v;
            if (oh) {
                __half2 h0 = __floats2half2_rn(v.x, v.y);
                __half2 h1 = __floats2half2_rn(v.z, v.w);
                float2 f0 = __half22float2(h0);
                float2 f1 = __half22float2(h1);
                __half2 l0 = __floats2half2_rn(v.x - f0.x, v.y - f0.y);
                __half2 l1 = __floats2half2_rn(v.z - f1.x, v.w - f1.y);
                *(uint2*)(oh + (size_t)gm * D + q * 4) =
                    make_uint2(*(unsigned*)&h0, *(unsigned*)&h1);
                *(uint2*)(ol + (size_t)gm * D + q * 4) =
                    make_uint2(*(unsigned*)&l0, *(unsigned*)&l1);
            }
        }
    }
}

// ---------------------------------------------------------------------------
extern "C" void kernel_launch(void* const* d_in, const int* in_sizes, int n_in,
                              void* d_out, int out_size) {
    const float* x   = (const float*)d_in[0];
    const int*   ei  = (const int*)  d_in[1];
    const float* W1l = (const float*)d_in[2];
    const float* b1l = (const float*)d_in[3];
    const float* W1r = (const float*)d_in[4];
    const float* W2l = (const float*)d_in[5];
    const float* b2l = (const float*)d_in[6];
    const float* W2r = (const float*)d_in[7];
    float* out = (float*)d_out;

    int n_nodes = in_sizes[0] / D;
    int n_edges = in_sizes[1] / 2;
    const int* src = ei;
    const int* dst = ei + n_edges;

    __half *mh, *ml, *xh, *xl, *w16;
    int *deg, *rowptr, *cursor, *csr, *bsums, *boffs;
    cudaGetSymbolAddress((void**)&mh,     g_meanh);
    cudaGetSymbolAddress((void**)&ml,     g_meanl);
    cudaGetSymbolAddress((void**)&xh,     g_xh);
    cudaGetSymbolAddress((void**)&xl,     g_xl);
    cudaGetSymbolAddress((void**)&w16,    g_w16);
    cudaGetSymbolAddress((void**)&deg,    g_deg);
    cudaGetSymbolAddress((void**)&rowptr, g_rowptr);
    cudaGetSymbolAddress((void**)&cursor, g_cursor);
    cudaGetSymbolAddress((void**)&csr,    g_csrsrc);
    cudaGetSymbolAddress((void**)&bsums,  g_blocksums);
    cudaGetSymbolAddress((void**)&boffs,  g_blockoffs);

    const int EPI_SMEM = 4 * 32 * EPI_LD * (int)sizeof(float);  // ~34.8 KB
    cudaFuncSetAttribute(combine_wmma,
                         cudaFuncAttributeMaxDynamicSharedMemorySize, EPI_SMEM);

    int eblocks = (n_edges + 255) / 256;
    int nscan = (n_nodes + 1023) / 1024;
    int nblocks = (n_nodes + 255) / 256;
    int npairs = (n_nodes + 1) / 2;
    int ablocks = (npairs * 32 + 255) / 256;
    int cblocks = (n_nodes + TILE - 1) / TILE;
    int n4 = n_nodes * D / 4;
    int vblocks = (n4 + 255) / 256;

    // ---- CSR build + conversions ----
    cudaMemsetAsync(deg, 0, (size_t)n_nodes * sizeof(int));
    convert_kernel<<<vblocks, 256>>>((const float4*)x, (uint2*)xh, (uint2*)xl, n4);
    wsplit_kernel<<<16, 256>>>(W1l, W1r, W2l, W2r, w16);
    count_kernel<<<eblocks, 256>>>(dst, deg, n_edges);
    scan_kernel<<<nscan, 1024>>>(deg, rowptr, bsums, n_nodes);
    scan_kernel<<<1, 1024>>>(bsums, boffs, nullptr, nscan);
    add_off_kernel<<<nblocks, 256>>>(rowptr, cursor, boffs, n_nodes);
    fill_kernel<<<eblocks, 256>>>(src, dst, cursor, csr, n_edges);

    // ---- Layer 1: mean of x -> h (emitted as hi/lo fp16 into xh/xl) ----
    aggregate_kernel<<<ablocks, 256>>>((const uint2*)xh, csr, rowptr, deg,
                                       mh, ml, n_nodes);
    combine_wmma<<<cblocks, 128, EPI_SMEM>>>(mh, ml, xh, xl,
                                             w16 + 0 * 4 * 4096, b1l,
                                             nullptr, xh, xl, n_nodes, 1);

    // ---- Layer 2: mean of h -> out (fp32) ----
    aggregate_kernel<<<ablocks, 256>>>((const uint2*)xh, csr, rowptr, deg,
                                       mh, ml, n_nodes);
    combine_wmma<<<cblocks, 128, EPI_SMEM>>>(mh, ml, xh, xl,
                                             w16 + 1 * 4 * 4096, b2l,
                                             out, nullptr, nullptr, n_nodes, 0);
}